// round 9
// baseline (speedup 1.0000x reference)
#include <cuda_runtime.h>
#include <cstdint>

// Problem geometry (fixed for this dataset instance)
#define CC    3
#define HH    496
#define WW    432
#define HWSZ  (HH * WW)            // 214272
#define PLANE (CC * HWSZ)          // 642816
#define MAXB  8
#define NBUCK 8192                 // ordered_bits >> 19
#define NSH   4                    // histogram shards (contention relief)
#define CAP   4096                 // candidate buffer per batch
#define SURVCAP 131072             // survivor buffer per batch (expect ~72K)
#define TILE_BLOCKS ((PLANE + 1023) / 1024)   // 628 tiles of 1024 px per batch
#define NBLK  128                  // persistent blocks (<= 148 SMs, guaranteed resident)

// One contiguous zeroed scratch region: hist + counters + arrive flags.
#define HIST_INTS   (MAXB * NSH * NBUCK)       // 262144 ints = 1 MB
#define SCOUNT_OFF  (HIST_INTS)                // 8 ints
#define COUNT_OFF   (HIST_INTS + MAXB)         // 8 ints
#define ARRIVE_OFF  (HIST_INTS + 2 * MAXB)     // 4 ints
#define ZERO_INTS   (HIST_INTS + 2 * MAXB + 4)

__device__ int                g_zero[ZERO_INTS];
__device__ int                g_thresh[MAXB];
__device__ unsigned long long g_surv[MAXB * SURVCAP];   // 8 MB
__device__ unsigned long long g_cand[MAXB * CAP];

__device__ __forceinline__ float sigclip(float x) {
    float s = 1.0f / (1.0f + __expf(-x));
    return fminf(fmaxf(s, 1.0e-4f), 1.0f - 1.0e-4f);
}

// total-order key for floats (monotone map to uint32, ascending)
__device__ __forceinline__ unsigned int ordkey(float v) {
    unsigned int bits = __float_as_uint(v);
    return bits ^ ((unsigned int)((int)bits >> 31) | 0x80000000u);
}

// Software grid barrier. Safe because all NBLK blocks are co-resident
// (NBLK <= SM count, 1 small block per SM always fits).
__device__ __forceinline__ void gsync(int phase) {
    __syncthreads();
    if (threadIdx.x == 0) {
        __threadfence();
        atomicAdd(&g_zero[ARRIVE_OFF + phase], 1);
        while (atomicAdd(&g_zero[ARRIVE_OFF + phase], 0) < NBLK) { }
    }
    __syncthreads();
}

__global__ __launch_bounds__(256)
void fused(const float* __restrict__ hm,
           const float* __restrict__ cen_offset,
           const float* __restrict__ direction,
           const float* __restrict__ z_coor,
           const float* __restrict__ dimf,
           float* __restrict__ out,
           int B, int K) {
    __shared__ int s_cnt, s_base;
    __shared__ int merged[NBUCK];     // 32 KB (phase B only)
    __shared__ int suf[256];
    int tid = threadIdx.x;

    // ===================== Phase A: NMS + hist + survivors =====================
    int ntile = B * TILE_BLOCKS;
    for (int t = blockIdx.x; t < ntile; t += NBLK) {
        int b    = t / TILE_BLOCKS;
        int base = (t - b * TILE_BLOCKS) * 1024 + tid * 4;
        int sh   = tid & (NSH - 1);

        if (tid == 0) s_cnt = 0;
        __syncthreads();

        unsigned long long mykeys[4];
        int myn = 0;

        if (base < PLANE) {
            const float* plane = hm + (size_t)b * PLANE;
            int hw = base % HWSZ;
            int h  = hw / WW;
            int w  = hw % WW;
            const float* p = plane + base;
            const float NEG = -3.4e38f;

            float rc[6], ru[6], rd[6];
            float4 c4 = *reinterpret_cast<const float4*>(p);
            rc[0] = (w > 0)      ? p[-1] : NEG;
            rc[1] = c4.x; rc[2] = c4.y; rc[3] = c4.z; rc[4] = c4.w;
            rc[5] = (w + 4 < WW) ? p[4]  : NEG;

            if (h > 0) {
                const float* q = p - WW;
                float4 u4 = *reinterpret_cast<const float4*>(q);
                ru[0] = (w > 0) ? q[-1] : NEG;
                ru[1] = u4.x; ru[2] = u4.y; ru[3] = u4.z; ru[4] = u4.w;
                ru[5] = (w + 4 < WW) ? q[4] : NEG;
            } else {
                #pragma unroll
                for (int j = 0; j < 6; j++) ru[j] = NEG;
            }
            if (h + 1 < HH) {
                const float* q = p + WW;
                float4 d4 = *reinterpret_cast<const float4*>(q);
                rd[0] = (w > 0) ? q[-1] : NEG;
                rd[1] = d4.x; rd[2] = d4.y; rd[3] = d4.z; rd[4] = d4.w;
                rd[5] = (w + 4 < WW) ? q[4] : NEG;
            } else {
                #pragma unroll
                for (int j = 0; j < 6; j++) rd[j] = NEG;
            }

            #pragma unroll
            for (int j = 0; j < 4; j++) {
                float v = rc[j + 1];
                float m = fmaxf(rc[j], rc[j + 2]);
                m = fmaxf(m, fmaxf(fmaxf(ru[j], ru[j + 1]), ru[j + 2]));
                m = fmaxf(m, fmaxf(fmaxf(rd[j], rd[j + 1]), rd[j + 2]));
                if (v >= m) {                      // keep iff no neighbor > v
                    unsigned int ord = ordkey(v);
                    atomicAdd(&g_zero[(b * NSH + sh) * NBUCK + (int)(ord >> 19)], 1);
                    unsigned int idx = (unsigned int)(base + j);   // c*HW + hw
                    mykeys[myn++] = ((unsigned long long)ord << 32) |
                                    (unsigned long long)(~idx);
                }
            }
        }

        int local = 0;
        if (myn) local = atomicAdd(&s_cnt, myn);
        __syncthreads();
        if (tid == 0) s_base = atomicAdd(&g_zero[SCOUNT_OFF + b], s_cnt);
        __syncthreads();
        if (myn) {
            int pos = s_base + local;
            for (int j = 0; j < myn; j++) {
                int pp = pos + j;
                if (pp < SURVCAP) g_surv[b * SURVCAP + pp] = mykeys[j];
            }
        }
        __syncthreads();   // protect s_base until all flushes done
    }

    gsync(0);

    // ===================== Phase B: threshold select =====================
    if (blockIdx.x < (unsigned)B) {
        int b = blockIdx.x;
        int s = 0;
        #pragma unroll 1
        for (int j = 0; j < 32; j++) {
            int bk = tid * 32 + j;
            int v = 0;
            #pragma unroll
            for (int sh = 0; sh < NSH; sh++)
                v += __ldcg(&g_zero[(b * NSH + sh) * NBUCK + bk]);
            merged[bk] = v;
            s += v;
        }
        suf[tid] = s;
        __syncthreads();

        // Hillis-Steele inclusive suffix sum over 256 chunks
        #pragma unroll
        for (int off = 1; off < 256; off <<= 1) {
            int v = (tid + off < 256) ? suf[tid + off] : 0;
            __syncthreads();
            suf[tid] += v;
            __syncthreads();
        }

        if (tid == 0 && suf[0] < K) g_thresh[b] = 0;
        int snext = (tid < 255) ? suf[tid + 1] : 0;
        if (suf[tid] >= K && snext < K) {
            int cum = snext;
            int T = tid * 32;
            for (int j = 31; j >= 0; j--) {
                cum += merged[tid * 32 + j];
                if (cum >= K) { T = tid * 32 + j; break; }
            }
            g_thresh[b] = T;
        }
    }

    gsync(1);

    // ===================== Phase C: collect candidates =====================
    int nunitsC = B * (SURVCAP / 1024);
    for (int u = blockIdx.x; u < nunitsC; u += NBLK) {
        int b    = u / (SURVCAP / 1024);
        int base = (u - b * (SURVCAP / 1024)) * 1024 + tid * 4;
        int n = __ldcg(&g_zero[SCOUNT_OFF + b]);
        if (n > SURVCAP) n = SURVCAP;
        if (base >= n) continue;
        int T = __ldcg(&g_thresh[b]);

        const unsigned long long* sp = &g_surv[b * SURVCAP + base];
        #pragma unroll
        for (int j = 0; j < 4; j++) {
            if (base + j >= n) break;
            unsigned long long key = __ldcg(&sp[j]);
            if ((int)(key >> 51) >= T) {
                int pos = atomicAdd(&g_zero[COUNT_OFF + b], 1);
                if (pos < CAP) g_cand[b * CAP + pos] = key;
            }
        }
    }

    gsync(2);

    // ===================== Phase D: rank + gather =====================
    int lane = tid & 31;
    int warp = tid >> 5;
    int nunitsD = B * (CAP / 8);
    for (int u = blockIdx.x; u < nunitsD; u += NBLK) {
        int b = u / (CAP / 8);
        int g = u - b * (CAP / 8);
        int n = __ldcg(&g_zero[COUNT_OFF + b]);
        if (n > CAP) n = CAP;
        if (g * 8 >= n) continue;

        int cand = g * 8 + warp;
        if (cand >= n) continue;

        const unsigned long long* cp = &g_cand[b * CAP];
        unsigned long long key = __ldcg(&cp[cand]);

        int rank = 0;
        for (int j = lane; j < n; j += 32)
            rank += (__ldcg(&cp[j]) > key);
        rank = __reduce_add_sync(0xFFFFFFFFu, rank);
        if (rank >= K) continue;

        if (lane == 0) {
            unsigned int ord  = (unsigned int)(key >> 32);
            unsigned int bits = (ord & 0x80000000u) ? (ord ^ 0x80000000u) : ~ord;
            float score = sigclip(__uint_as_float(bits));
            unsigned int idx = ~((unsigned int)key);       // c*HW + hw
            int c  = (int)(idx / HWSZ);
            int hw = (int)(idx - (unsigned int)c * HWSZ);
            int r  = hw / WW;
            int w  = hw - r * WW;

            const float* off = cen_offset + (size_t)b * 2 * HWSZ;
            const float* dir = direction  + (size_t)b * 2 * HWSZ;
            const float* zc  = z_coor     + (size_t)b * 1 * HWSZ;
            const float* dm  = dimf       + (size_t)b * 3 * HWSZ;

            float* o = out + ((size_t)b * K + rank) * 10;
            o[0] = score;
            o[1] = (float)w + sigclip(off[hw]);
            o[2] = (float)r + sigclip(off[HWSZ + hw]);
            o[3] = zc[hw];
            o[4] = dm[hw];
            o[5] = dm[HWSZ + hw];
            o[6] = dm[2 * HWSZ + hw];
            o[7] = dir[hw];
            o[8] = dir[HWSZ + hw];
            o[9] = (float)c;
        }
    }
}

// ---------------------------------------------------------------------------
// Host launcher
// ---------------------------------------------------------------------------
extern "C" void kernel_launch(void* const* d_in, const int* in_sizes, int n_in,
                              void* d_out, int out_size) {
    const float* hm   = (const float*)d_in[0];
    const float* off  = (const float*)d_in[1];
    const float* dir  = (const float*)d_in[2];
    const float* zc   = (const float*)d_in[3];
    const float* dm   = (const float*)d_in[4];
    float* out = (float*)d_out;

    int B = in_sizes[0] / PLANE;
    if (B < 1) B = 1;
    if (B > MAXB) B = MAXB;
    int K = out_size / (B * 10);
    if (K < 1) K = 1;

    void* zptr = nullptr;
    cudaGetSymbolAddress(&zptr, g_zero);
    cudaMemsetAsync(zptr, 0, ZERO_INTS * sizeof(int), 0);
    cudaMemsetAsync(d_out, 0, (size_t)out_size * sizeof(float), 0);

    fused<<<NBLK, 256>>>(hm, off, dir, zc, dm, out, B, K);
}

// round 11
// speedup vs baseline: 1.9192x; 1.9192x over previous
#include <cuda_runtime.h>
#include <cstdint>

// Problem geometry (fixed for this dataset instance)
#define CC    3
#define HH    496
#define WW    432
#define HWSZ  (HH * WW)            // 214272
#define PLANE (CC * HWSZ)          // 642816
#define MAXB  8
#define NBUCK 8192                 // ordered_bits >> 19
#define NSH   4                    // histogram shards (contention relief)
#define CAP   4096                 // candidate buffer per batch
#define SURVCAP 131072             // survivor buffer per batch (expect ~72K)
#define K1_BLOCKS ((PLANE + 2047) / 2048)   // 314 blocks of 256 thr x 8 px
#define SKEYS 768                  // smem staging cap (theoretical max 512/tile)
#define K4_WPB 8                   // warps (candidates) per k4 block

// One contiguous zeroed scratch region: hist[b][sh][bucket] then counters.
#define HIST_INTS   (MAXB * NSH * NBUCK)       // 262144 ints = 1 MB
#define SCOUNT_OFF  (HIST_INTS)                // 8 ints
#define COUNT_OFF   (HIST_INTS + MAXB)         // 8 ints
#define ZERO_INTS   (HIST_INTS + 2 * MAXB)

__device__ int                g_zero[ZERO_INTS];
__device__ int                g_thresh[MAXB];
__device__ unsigned long long g_surv[MAXB * SURVCAP];   // 8 MB
__device__ unsigned long long g_cand[MAXB * CAP];

__device__ __forceinline__ float sigclip(float x) {
    float s = 1.0f / (1.0f + __expf(-x));
    return fminf(fmaxf(s, 1.0e-4f), 1.0f - 1.0e-4f);
}

// total-order key for floats (monotone map to uint32, ascending)
__device__ __forceinline__ unsigned int ordkey(float v) {
    unsigned int bits = __float_as_uint(v);
    return bits ^ ((unsigned int)((int)bits >> 31) | 0x80000000u);
}

// ---------------------------------------------------------------------------
// K1: raw-domain 3x3 NMS -> survivor list + sharded hist.
//     8 px/thread (two float4 per row: 12 LDG per 8 px).
//     Survivors staged in smem via warp-aggregated ballot (no local arrays,
//     no per-thread smem atomic contention), flushed coalesced per block.
// ---------------------------------------------------------------------------
__global__ __launch_bounds__(256)
void k1_nms(const float* __restrict__ hm) {
    int b    = blockIdx.y;
    int base = blockIdx.x * 2048 + threadIdx.x * 8;   // within plane
    int sh   = threadIdx.x & (NSH - 1);
    int lane = threadIdx.x & 31;

    __shared__ int s_cnt, s_base;
    __shared__ unsigned long long s_keys[SKEYS];
    if (threadIdx.x == 0) s_cnt = 0;
    __syncthreads();

    float rc[10], ru[10], rd[10];
    bool active = (base < PLANE);

    if (active) {
        const float* plane = hm + (size_t)b * PLANE;
        int hw = base % HWSZ;
        int h  = hw / WW;
        int w  = hw % WW;
        const float* p = plane + base;
        const float NEG = -3.4e38f;

        {
            float4 a = *reinterpret_cast<const float4*>(p);
            float4 c = *reinterpret_cast<const float4*>(p + 4);
            rc[1]=a.x; rc[2]=a.y; rc[3]=a.z; rc[4]=a.w;
            rc[5]=c.x; rc[6]=c.y; rc[7]=c.z; rc[8]=c.w;
            rc[0] = (w > 0)      ? p[-1] : NEG;
            rc[9] = (w + 8 < WW) ? p[8]  : NEG;
        }
        if (h > 0) {
            const float* q = p - WW;
            float4 a = *reinterpret_cast<const float4*>(q);
            float4 c = *reinterpret_cast<const float4*>(q + 4);
            ru[1]=a.x; ru[2]=a.y; ru[3]=a.z; ru[4]=a.w;
            ru[5]=c.x; ru[6]=c.y; ru[7]=c.z; ru[8]=c.w;
            ru[0] = (w > 0)      ? q[-1] : NEG;
            ru[9] = (w + 8 < WW) ? q[8]  : NEG;
        } else {
            #pragma unroll
            for (int j = 0; j < 10; j++) ru[j] = NEG;
        }
        if (h + 1 < HH) {
            const float* q = p + WW;
            float4 a = *reinterpret_cast<const float4*>(q);
            float4 c = *reinterpret_cast<const float4*>(q + 4);
            rd[1]=a.x; rd[2]=a.y; rd[3]=a.z; rd[4]=a.w;
            rd[5]=c.x; rd[6]=c.y; rd[7]=c.z; rd[8]=c.w;
            rd[0] = (w > 0)      ? q[-1] : NEG;
            rd[9] = (w + 8 < WW) ? q[8]  : NEG;
        } else {
            #pragma unroll
            for (int j = 0; j < 10; j++) rd[j] = NEG;
        }
    }

    // Warp-aggregated survivor emission: one smem atomic per warp per j.
    #pragma unroll
    for (int j = 0; j < 8; j++) {
        bool keep = false;
        unsigned long long key = 0;
        if (active) {
            float v = rc[j + 1];
            float m = fmaxf(rc[j], rc[j + 2]);
            m = fmaxf(m, fmaxf(fmaxf(ru[j], ru[j + 1]), ru[j + 2]));
            m = fmaxf(m, fmaxf(fmaxf(rd[j], rd[j + 1]), rd[j + 2]));
            if (v >= m) {
                keep = true;
                unsigned int ord = ordkey(v);
                atomicAdd(&g_zero[(b * NSH + sh) * NBUCK + (int)(ord >> 19)], 1);
                unsigned int idx = (unsigned int)(base + j);   // c*HW + hw
                key = ((unsigned long long)ord << 32) |
                      (unsigned long long)(~idx);
            }
        }
        unsigned mask = __ballot_sync(0xFFFFFFFFu, keep);
        if (mask) {
            int leader = __ffs(mask) - 1;
            int wbase = 0;
            if (lane == leader) wbase = atomicAdd(&s_cnt, __popc(mask));
            wbase = __shfl_sync(0xFFFFFFFFu, wbase, leader);
            if (keep) {
                int pos = wbase + __popc(mask & ((1u << lane) - 1));
                if (pos < SKEYS) s_keys[pos] = key;
            }
        }
    }

    __syncthreads();
    if (threadIdx.x == 0)
        s_base = atomicAdd(&g_zero[SCOUNT_OFF + b], s_cnt);
    __syncthreads();

    int nblk  = (s_cnt < SKEYS) ? s_cnt : SKEYS;
    int gbase = s_base;
    for (int i = threadIdx.x; i < nblk; i += 256) {
        int pp = gbase + i;
        if (pp < SURVCAP) g_surv[b * SURVCAP + pp] = s_keys[i];
    }
}

// ---------------------------------------------------------------------------
// K2: per-batch threshold bucket via parallel suffix scan
// ---------------------------------------------------------------------------
__global__ void k2_thresh(int K) {
    int b = blockIdx.x;
    __shared__ int suf[256];
    __shared__ int merged[NBUCK];       // 32 KB: shard-summed histogram
    int t = threadIdx.x;                // 256 threads, 32 buckets each
    int s = 0;
    #pragma unroll 1
    for (int j = 0; j < 32; j++) {
        int bk = t * 32 + j;
        int v = 0;
        #pragma unroll
        for (int sh = 0; sh < NSH; sh++)
            v += g_zero[(b * NSH + sh) * NBUCK + bk];
        merged[bk] = v;
        s += v;
    }
    suf[t] = s;
    __syncthreads();

    // Hillis-Steele inclusive suffix sum over 256 chunks
    #pragma unroll
    for (int off = 1; off < 256; off <<= 1) {
        int v = (t + off < 256) ? suf[t + off] : 0;
        __syncthreads();
        suf[t] += v;
        __syncthreads();
    }

    if (t == 0 && suf[0] < K) g_thresh[b] = 0;   // fewer than K total
    int snext = (t < 255) ? suf[t + 1] : 0;
    if (suf[t] >= K && snext < K) {
        int cum = snext;
        int T = t * 32;
        for (int j = 31; j >= 0; j--) {
            cum += merged[t * 32 + j];
            if (cum >= K) { T = t * 32 + j; break; }
        }
        g_thresh[b] = T;   // collect criterion: bucket >= T
    }
}

// ---------------------------------------------------------------------------
// K3: filter survivor list by threshold bucket into candidate arrays
//     4 consecutive keys per thread (two ulonglong2 loads)
// ---------------------------------------------------------------------------
__global__ __launch_bounds__(256)
void k3_collect() {
    int b    = blockIdx.y;
    int base = (blockIdx.x * 256 + threadIdx.x) * 4;
    int n = g_zero[SCOUNT_OFF + b];
    if (n > SURVCAP) n = SURVCAP;
    if (base >= n) return;
    int T = g_thresh[b];

    const ulonglong2* sp =
        reinterpret_cast<const ulonglong2*>(&g_surv[b * SURVCAP + base]);
    ulonglong2 v0 = sp[0];
    ulonglong2 v1 = sp[1];
    unsigned long long kk[4] = { v0.x, v0.y, v1.x, v1.y };

    #pragma unroll
    for (int j = 0; j < 4; j++) {
        if (base + j >= n) break;
        unsigned long long key = kk[j];
        if ((int)(key >> 51) >= T) {
            int pos = atomicAdd(&g_zero[COUNT_OFF + b], 1);
            if (pos < CAP) g_cand[b * CAP + pos] = key;
        }
    }
}

// ---------------------------------------------------------------------------
// K4: warp-per-candidate rank selection, direct global reads (L2-resident).
//     Keys unique -> rank(key) = #{j: keys[j] > key} is a bijection.
// ---------------------------------------------------------------------------
__global__ __launch_bounds__(32 * K4_WPB)
void k4_rank_gather(const float* __restrict__ cen_offset,
                    const float* __restrict__ direction,
                    const float* __restrict__ z_coor,
                    const float* __restrict__ dimf,
                    float* __restrict__ out,
                    int K) {
    int b    = blockIdx.y;
    int lane = threadIdx.x & 31;
    int cand = blockIdx.x * K4_WPB + (threadIdx.x >> 5);
    int n    = g_zero[COUNT_OFF + b];
    if (n > CAP) n = CAP;
    if (cand >= n) return;

    const unsigned long long* cp = &g_cand[b * CAP];
    unsigned long long key = cp[cand];

    int rank = 0;
    for (int j = lane; j < n; j += 32)
        rank += (cp[j] > key);
    rank = __reduce_add_sync(0xFFFFFFFFu, rank);
    if (rank >= K) return;

    if (lane == 0) {
        unsigned int ord  = (unsigned int)(key >> 32);
        unsigned int bits = (ord & 0x80000000u) ? (ord ^ 0x80000000u) : ~ord;
        float score = sigclip(__uint_as_float(bits));
        unsigned int idx = ~((unsigned int)key);       // c*HW + hw
        int c  = (int)(idx / HWSZ);
        int hw = (int)(idx - (unsigned int)c * HWSZ);
        int r  = hw / WW;
        int w  = hw - r * WW;

        const float* off = cen_offset + (size_t)b * 2 * HWSZ;
        const float* dir = direction  + (size_t)b * 2 * HWSZ;
        const float* zc  = z_coor     + (size_t)b * 1 * HWSZ;
        const float* dm  = dimf       + (size_t)b * 3 * HWSZ;

        float* o = out + ((size_t)b * K + rank) * 10;
        o[0] = score;
        o[1] = (float)w + sigclip(off[hw]);
        o[2] = (float)r + sigclip(off[HWSZ + hw]);
        o[3] = zc[hw];
        o[4] = dm[hw];
        o[5] = dm[HWSZ + hw];
        o[6] = dm[2 * HWSZ + hw];
        o[7] = dir[hw];
        o[8] = dir[HWSZ + hw];
        o[9] = (float)c;
    }
}

// ---------------------------------------------------------------------------
// Host launcher
// ---------------------------------------------------------------------------
extern "C" void kernel_launch(void* const* d_in, const int* in_sizes, int n_in,
                              void* d_out, int out_size) {
    const float* hm   = (const float*)d_in[0];
    const float* off  = (const float*)d_in[1];
    const float* dir  = (const float*)d_in[2];
    const float* zc   = (const float*)d_in[3];
    const float* dm   = (const float*)d_in[4];
    float* out = (float*)d_out;

    int B = in_sizes[0] / PLANE;
    if (B < 1) B = 1;
    if (B > MAXB) B = MAXB;
    int K = out_size / (B * 10);
    if (K < 1) K = 1;

    void* zptr = nullptr;
    cudaGetSymbolAddress(&zptr, g_zero);
    cudaMemsetAsync(zptr, 0, ZERO_INTS * sizeof(int), 0);
    cudaMemsetAsync(d_out, 0, (size_t)out_size * sizeof(float), 0);

    k1_nms<<<dim3(K1_BLOCKS, B), 256>>>(hm);
    k2_thresh<<<B, 256>>>(K);
    k3_collect<<<dim3(SURVCAP / 1024, B), 256>>>();
    k4_rank_gather<<<dim3(CAP / K4_WPB, B), 32 * K4_WPB>>>(off, dir, zc, dm, out, K);
}